// round 3
// baseline (speedup 1.0000x reference)
#include <cuda_runtime.h>

// Problem constants (fixed by the dataset)
#define NODES   262144
#define BGRAPH  1024
#define NPG     256
#define HID     192
#define HID2    384
#define NEDGE   4194304
#define KKEEP   231          // ceil(0.9 * 256)
#define LN_EPS  1e-5f

// Scratch (device globals — no allocations allowed)
__device__ float         d_keep[NODES];
__device__ unsigned char d_touched[NODES];

// ---------------------------------------------------------------------------
// f32x2 packed helpers (sm_103a FFMA2 — PTX-only, doubles fp32 FMA throughput)
// ---------------------------------------------------------------------------
__device__ __forceinline__ unsigned long long pk2(float lo, float hi) {
    unsigned long long r;
    asm("mov.b64 %0, {%1, %2};" : "=l"(r) : "f"(lo), "f"(hi));
    return r;
}
__device__ __forceinline__ void upk2(unsigned long long v, float& lo, float& hi) {
    asm("mov.b64 {%0, %1}, %2;" : "=f"(lo), "=f"(hi) : "l"(v));
}
__device__ __forceinline__ void fma2(unsigned long long& acc,
                                     unsigned long long a, unsigned long long b) {
    asm("fma.rn.f32x2 %0, %1, %2, %0;" : "+l"(acc) : "l"(a), "l"(b));
}

// ---------------------------------------------------------------------------
// Kernel 1: fused node head
//   x = h + g[graph];  z = x@W1 + b1;  LN;  relu;  logits = z@W2 + b2
// Block = 256 threads, BM = 64 nodes (one graph slice; 64 | 256 so a block
// never crosses a graph boundary). Warp w owns nodes [8w, 8w+8); lane c owns
// columns {c, c+32, ..., c+352}. Accumulators: 4 node-pairs x 12 cols as f32x2.
// K staged in chunks of 16 with register prefetch (software pipeline).
// ---------------------------------------------------------------------------
__global__ void __launch_bounds__(256, 1)
head_kernel(const float* __restrict__ h,  const float* __restrict__ g,
            const float* __restrict__ W1, const float* __restrict__ b1,
            const float* __restrict__ lngamma, const float* __restrict__ lnbeta,
            const float* __restrict__ W2, const float* __restrict__ b2,
            float* __restrict__ logits_out)
{
    __shared__ float Xs[64][16];      // [node][k]     4 KB
    __shared__ float Ws[16][HID2];    // [k][col]     24 KB

    const int tid  = threadIdx.x;
    const int lane = tid & 31;
    const int warp = tid >> 5;
    const int n0   = blockIdx.x * 64;
    const int graph = n0 >> 8;

    const float4* h4  = (const float4*)h;                    // 48 float4 / row
    const float4* g4  = (const float4*)(g + graph * HID);
    const float4* w14 = (const float4*)W1;                   // 96 float4 / row

    const int node_x = tid >> 2;       // X loader: 4 threads per node
    const int quad_x = tid & 3;        // each loads one float4 (16 floats/node/stage)

    // ---- prefetch stage 0 into registers ----
    float4 hx = h4[(n0 + node_x) * 48 + quad_x];
    float4 gx = g4[quad_x];
    float4 wp[6];
#pragma unroll
    for (int it = 0; it < 6; it++) {
        int q = tid + it * 256;                  // 1536 float4 per W stage
        wp[it] = w14[(q / 96) * 96 + (q % 96)];
    }

    // ---- accumulators, init with b1 ----
    unsigned long long acc[4][12];
#pragma unroll
    for (int j = 0; j < 12; j++) {
        float bv = b1[lane + 32 * j];
        unsigned long long p = pk2(bv, bv);
#pragma unroll
        for (int i = 0; i < 4; i++) acc[i][j] = p;
    }

    // ---- main loop over K in chunks of 16 ----
    int k0 = 0;
    for (;;) {
        __syncthreads();   // previous stage's smem readers done
        {
            float4 xv;
            xv.x = hx.x + gx.x; xv.y = hx.y + gx.y;
            xv.z = hx.z + gx.z; xv.w = hx.w + gx.w;
            *(float4*)&Xs[node_x][quad_x * 4] = xv;
#pragma unroll
            for (int it = 0; it < 6; it++) {
                int q = tid + it * 256;
                *(float4*)&Ws[q / 96][(q % 96) * 4] = wp[it];
            }
        }
        __syncthreads();

        const int k0n = k0 + 16;
        if (k0n < HID) {   // prefetch next stage (latency hidden by compute)
            hx = h4[(n0 + node_x) * 48 + (k0n >> 2) + quad_x];
            gx = g4[(k0n >> 2) + quad_x];
#pragma unroll
            for (int it = 0; it < 6; it++) {
                int q = tid + it * 256;
                wp[it] = w14[(k0n + q / 96) * 96 + (q % 96)];
            }
        }

#pragma unroll
        for (int kk = 0; kk < 16; kk++) {
            unsigned long long xp[4];
#pragma unroll
            for (int i = 0; i < 4; i++)       // warp-broadcast LDS (conflict-free)
                xp[i] = pk2(Xs[8 * warp + 2 * i][kk], Xs[8 * warp + 2 * i + 1][kk]);
#pragma unroll
            for (int j = 0; j < 12; j++) {    // lane-striped LDS (conflict-free)
                float wv = Ws[kk][lane + 32 * j];
                unsigned long long wd = pk2(wv, wv);
#pragma unroll
                for (int i = 0; i < 4; i++) fma2(acc[i][j], xp[i], wd);
            }
        }

        k0 = k0n;
        if (k0 >= HID) break;
    }

    // ---- epilogue: LayerNorm + ReLU + dot(W2) per node, warp-local ----
    float gam[12], bet[12], w2r[12];
#pragma unroll
    for (int j = 0; j < 12; j++) {
        int c = lane + 32 * j;
        gam[j] = lngamma[c]; bet[j] = lnbeta[c]; w2r[j] = W2[c];
    }
    const float b2v = b2[0];

#pragma unroll
    for (int n = 0; n < 8; n++) {
        const int i = n >> 1;
        float z[12];
#pragma unroll
        for (int j = 0; j < 12; j++) {
            float lo, hi;
            upk2(acc[i][j], lo, hi);
            z[j] = (n & 1) ? hi : lo;
        }
        float s1 = 0.f, s2 = 0.f;
#pragma unroll
        for (int j = 0; j < 12; j++) { s1 += z[j]; s2 += z[j] * z[j]; }
#pragma unroll
        for (int d = 16; d > 0; d >>= 1) {
            s1 += __shfl_xor_sync(0xffffffffu, s1, d);
            s2 += __shfl_xor_sync(0xffffffffu, s2, d);
        }
        const float mu  = s1 * (1.0f / HID2);
        const float var = s2 * (1.0f / HID2) - mu * mu;
        const float inv = rsqrtf(var + LN_EPS);
        float t = 0.f;
#pragma unroll
        for (int j = 0; j < 12; j++) {
            float zz = (z[j] - mu) * inv * gam[j] + bet[j];
            zz = fmaxf(zz, 0.f);
            t += zz * w2r[j];
        }
#pragma unroll
        for (int d = 16; d > 0; d >>= 1)
            t += __shfl_xor_sync(0xffffffffu, t, d);
        if (lane == 0)
            logits_out[n0 + 8 * warp + n] = t + b2v;
    }
}

// ---------------------------------------------------------------------------
// Kernel 2: per-graph exact top-k keep mask (rank by O(n^2) count, exact
// jax.lax.top_k tie semantics: ties broken by lower index). Also zeroes the
// touched[] scratch for this replay.
// ---------------------------------------------------------------------------
__global__ void __launch_bounds__(256)
topk_kernel(const float* __restrict__ logits)
{
    __shared__ float sv[NPG];
    const int gidx = blockIdx.x;
    const int t = threadIdx.x;
    const int node = gidx * NPG + t;
    const float v = logits[node];
    sv[t] = v;
    d_touched[node] = 0;
    __syncthreads();
    int rank = 0;
#pragma unroll 8
    for (int j = 0; j < NPG; j++) {
        const float u = sv[j];                 // warp-broadcast read
        rank += (u > v) || (u == v && j < t);
    }
    d_keep[node] = (rank < KKEEP) ? 1.0f : 0.0f;
}

// ---------------------------------------------------------------------------
// Kernel 3: edge masking + weights + touched flags (4 edges / thread, int4)
// ---------------------------------------------------------------------------
__global__ void __launch_bounds__(256)
edge_kernel(const int* __restrict__ ei, const float* __restrict__ lg,
            float* __restrict__ em, float* __restrict__ ew)
{
    const int idx = blockIdx.x * 256 + threadIdx.x;     // NEDGE/4 threads
    const int4 s = ((const int4*)ei)[idx];
    const int4 d = ((const int4*)(ei + NEDGE))[idx];

    float4 m, w;
    m.x = d_keep[s.x] * d_keep[d.x];
    m.y = d_keep[s.y] * d_keep[d.y];
    m.z = d_keep[s.z] * d_keep[d.z];
    m.w = d_keep[s.w] * d_keep[d.w];
    w.x = (lg[s.x] + lg[d.x]) * m.x;
    w.y = (lg[s.y] + lg[d.y]) * m.y;
    w.z = (lg[s.z] + lg[d.z]) * m.z;
    w.w = (lg[s.w] + lg[d.w]) * m.w;

    ((float4*)em)[idx] = m;
    ((float4*)ew)[idx] = w;

    if (m.x != 0.f) { d_touched[s.x] = 1; d_touched[d.x] = 1; }
    if (m.y != 0.f) { d_touched[s.y] = 1; d_touched[d.y] = 1; }
    if (m.z != 0.f) { d_touched[s.z] = 1; d_touched[d.z] = 1; }
    if (m.w != 0.f) { d_touched[s.w] = 1; d_touched[d.w] = 1; }
}

// ---------------------------------------------------------------------------
// Kernel 4: node_mask = touched > 0
// ---------------------------------------------------------------------------
__global__ void __launch_bounds__(256)
mask_kernel(float* __restrict__ nm)
{
    const int i = blockIdx.x * 256 + threadIdx.x;
    nm[i] = d_touched[i] ? 1.0f : 0.0f;
}

// ---------------------------------------------------------------------------
// Launch: outputs concatenated as f32 in reference return order:
//   [0,E) edge_mask | [E,2E) edge_weight | [2E,2E+N) logits | [..+N) node_mask
// ---------------------------------------------------------------------------
extern "C" void kernel_launch(void* const* d_in, const int* in_sizes, int n_in,
                              void* d_out, int out_size)
{
    const float* h       = (const float*)d_in[0];
    const float* g       = (const float*)d_in[1];
    const int*   ei      = (const int*)  d_in[2];
    const float* W1      = (const float*)d_in[3];
    const float* b1      = (const float*)d_in[4];
    const float* lngamma = (const float*)d_in[5];
    const float* lnbeta  = (const float*)d_in[6];
    const float* W2      = (const float*)d_in[7];
    const float* b2      = (const float*)d_in[8];

    float* out = (float*)d_out;
    float* em = out;
    float* ew = out + (size_t)NEDGE;
    float* lg = out + 2 * (size_t)NEDGE;
    float* nm = lg + NODES;

    head_kernel<<<NODES / 64, 256>>>(h, g, W1, b1, lngamma, lnbeta, W2, b2, lg);
    topk_kernel<<<BGRAPH, 256>>>(lg);
    edge_kernel<<<NEDGE / 1024, 256>>>(ei, lg, em, ew);
    mask_kernel<<<NODES / 256, 256>>>(nm);
}

// round 4
// speedup vs baseline: 1.0516x; 1.0516x over previous
#include <cuda_runtime.h>

// Problem constants (fixed by the dataset)
#define NODES   262144
#define BGRAPH  1024
#define NPG     256
#define HID     192
#define HID2    384
#define NEDGE   4194304
#define KKEEP   231          // ceil(0.9 * 256)
#define LN_EPS  1e-5f

// Scratch (device globals — no allocations allowed)
__device__ float         d_keep[NODES];
__device__ unsigned char d_touched[NODES];

// ---------------------------------------------------------------------------
// f32x2 packed helpers (sm_103a FFMA2 — PTX-only, doubles fp32 FMA throughput)
// ---------------------------------------------------------------------------
__device__ __forceinline__ unsigned long long pk2(float lo, float hi) {
    unsigned long long r;
    asm("mov.b64 %0, {%1, %2};" : "=l"(r) : "f"(lo), "f"(hi));
    return r;
}
__device__ __forceinline__ void upk2(unsigned long long v, float& lo, float& hi) {
    asm("mov.b64 {%0, %1}, %2;" : "=f"(lo), "=f"(hi) : "l"(v));
}
__device__ __forceinline__ void fma2(unsigned long long& acc,
                                     unsigned long long a, unsigned long long b) {
    asm("fma.rn.f32x2 %0, %1, %2, %0;" : "+l"(acc) : "l"(a), "l"(b));
}

// ---------------------------------------------------------------------------
// Kernel 1: fused node head
//   x = h + g[graph];  z = x@W1 + b1;  LN;  relu;  logits = z@W2 + b2
// Block = 256 threads, BM = 64 nodes (one graph slice; 64 | 256 so a block
// never crosses a graph boundary). Warp w owns nodes [8w, 8w+8); lane c owns
// columns {c, c+32, ..., c+352}. Accumulators: 4 node-pairs x 12 cols as f32x2.
// K staged in chunks of 16 with register prefetch (software pipeline).
// ---------------------------------------------------------------------------
__global__ void __launch_bounds__(256, 1)
head_kernel(const float* __restrict__ h,  const float* __restrict__ g,
            const float* __restrict__ W1, const float* __restrict__ b1,
            const float* __restrict__ lngamma, const float* __restrict__ lnbeta,
            const float* __restrict__ W2, const float* __restrict__ b2,
            float* __restrict__ logits_out)
{
    __shared__ float Xs[64][16];      // [node][k]     4 KB
    __shared__ float Ws[16][HID2];    // [k][col]     24 KB

    const int tid  = threadIdx.x;
    const int lane = tid & 31;
    const int warp = tid >> 5;
    const int n0   = blockIdx.x * 64;
    const int graph = n0 >> 8;

    const float4* h4  = (const float4*)h;                    // 48 float4 / row
    const float4* g4  = (const float4*)(g + graph * HID);
    const float4* w14 = (const float4*)W1;                   // 96 float4 / row

    const int node_x = tid >> 2;       // X loader: 4 threads per node
    const int quad_x = tid & 3;        // each loads one float4 (16 floats/node/stage)

    // ---- prefetch stage 0 into registers ----
    float4 hx = h4[(n0 + node_x) * 48 + quad_x];
    float4 gx = g4[quad_x];
    float4 wp[6];
#pragma unroll
    for (int it = 0; it < 6; it++) {
        int q = tid + it * 256;                  // 1536 float4 per W stage
        wp[it] = w14[(q / 96) * 96 + (q % 96)];
    }

    // ---- accumulators, init with b1 ----
    unsigned long long acc[4][12];
#pragma unroll
    for (int j = 0; j < 12; j++) {
        float bv = b1[lane + 32 * j];
        unsigned long long p = pk2(bv, bv);
#pragma unroll
        for (int i = 0; i < 4; i++) acc[i][j] = p;
    }

    // ---- main loop over K in chunks of 16 ----
    int k0 = 0;
    for (;;) {
        __syncthreads();   // previous stage's smem readers done
        {
            float4 xv;
            xv.x = hx.x + gx.x; xv.y = hx.y + gx.y;
            xv.z = hx.z + gx.z; xv.w = hx.w + gx.w;
            *(float4*)&Xs[node_x][quad_x * 4] = xv;
#pragma unroll
            for (int it = 0; it < 6; it++) {
                int q = tid + it * 256;
                *(float4*)&Ws[q / 96][(q % 96) * 4] = wp[it];
            }
        }
        __syncthreads();

        const int k0n = k0 + 16;
        if (k0n < HID) {   // prefetch next stage (latency hidden by compute)
            hx = h4[(n0 + node_x) * 48 + (k0n >> 2) + quad_x];
            gx = g4[(k0n >> 2) + quad_x];
#pragma unroll
            for (int it = 0; it < 6; it++) {
                int q = tid + it * 256;
                wp[it] = w14[(k0n + q / 96) * 96 + (q % 96)];
            }
        }

#pragma unroll
        for (int kk = 0; kk < 16; kk++) {
            unsigned long long xp[4];
#pragma unroll
            for (int i = 0; i < 4; i++)       // warp-broadcast LDS (conflict-free)
                xp[i] = pk2(Xs[8 * warp + 2 * i][kk], Xs[8 * warp + 2 * i + 1][kk]);
#pragma unroll
            for (int j = 0; j < 12; j++) {    // lane-striped LDS (conflict-free)
                float wv = Ws[kk][lane + 32 * j];
                unsigned long long wd = pk2(wv, wv);
#pragma unroll
                for (int i = 0; i < 4; i++) fma2(acc[i][j], xp[i], wd);
            }
        }

        k0 = k0n;
        if (k0 >= HID) break;
    }

    // ---- epilogue: LayerNorm + ReLU + dot(W2) per node, warp-local ----
    float gam[12], bet[12], w2r[12];
#pragma unroll
    for (int j = 0; j < 12; j++) {
        int c = lane + 32 * j;
        gam[j] = lngamma[c]; bet[j] = lnbeta[c]; w2r[j] = W2[c];
    }
    const float b2v = b2[0];

#pragma unroll
    for (int n = 0; n < 8; n++) {
        const int i = n >> 1;
        float z[12];
#pragma unroll
        for (int j = 0; j < 12; j++) {
            float lo, hi;
            upk2(acc[i][j], lo, hi);
            z[j] = (n & 1) ? hi : lo;
        }
        float s1 = 0.f, s2 = 0.f;
#pragma unroll
        for (int j = 0; j < 12; j++) { s1 += z[j]; s2 += z[j] * z[j]; }
#pragma unroll
        for (int d = 16; d > 0; d >>= 1) {
            s1 += __shfl_xor_sync(0xffffffffu, s1, d);
            s2 += __shfl_xor_sync(0xffffffffu, s2, d);
        }
        const float mu  = s1 * (1.0f / HID2);
        const float var = s2 * (1.0f / HID2) - mu * mu;
        const float inv = rsqrtf(var + LN_EPS);
        float t = 0.f;
#pragma unroll
        for (int j = 0; j < 12; j++) {
            float zz = (z[j] - mu) * inv * gam[j] + bet[j];
            zz = fmaxf(zz, 0.f);
            t += zz * w2r[j];
        }
#pragma unroll
        for (int d = 16; d > 0; d >>= 1)
            t += __shfl_xor_sync(0xffffffffu, t, d);
        if (lane == 0)
            logits_out[n0 + 8 * warp + n] = t + b2v;
    }
}

// ---------------------------------------------------------------------------
// Kernel 2: per-graph exact top-k keep mask (rank by O(n^2) count, exact
// jax.lax.top_k tie semantics: ties broken by lower index). Also zeroes the
// touched[] scratch for this replay.
// ---------------------------------------------------------------------------
__global__ void __launch_bounds__(256)
topk_kernel(const float* __restrict__ logits)
{
    __shared__ float sv[NPG];
    const int gidx = blockIdx.x;
    const int t = threadIdx.x;
    const int node = gidx * NPG + t;
    const float v = logits[node];
    sv[t] = v;
    d_touched[node] = 0;
    __syncthreads();
    int rank = 0;
#pragma unroll 8
    for (int j = 0; j < NPG; j++) {
        const float u = sv[j];                 // warp-broadcast read
        rank += (u > v) || (u == v && j < t);
    }
    d_keep[node] = (rank < KKEEP) ? 1.0f : 0.0f;
}

// ---------------------------------------------------------------------------
// Kernel 3: edge masking + weights + touched flags (4 edges / thread, int4)
// ---------------------------------------------------------------------------
__global__ void __launch_bounds__(256)
edge_kernel(const int* __restrict__ ei, const float* __restrict__ lg,
            float* __restrict__ em, float* __restrict__ ew)
{
    const int idx = blockIdx.x * 256 + threadIdx.x;     // NEDGE/4 threads
    const int4 s = ((const int4*)ei)[idx];
    const int4 d = ((const int4*)(ei + NEDGE))[idx];

    float4 m, w;
    m.x = d_keep[s.x] * d_keep[d.x];
    m.y = d_keep[s.y] * d_keep[d.y];
    m.z = d_keep[s.z] * d_keep[d.z];
    m.w = d_keep[s.w] * d_keep[d.w];
    w.x = (lg[s.x] + lg[d.x]) * m.x;
    w.y = (lg[s.y] + lg[d.y]) * m.y;
    w.z = (lg[s.z] + lg[d.z]) * m.z;
    w.w = (lg[s.w] + lg[d.w]) * m.w;

    ((float4*)em)[idx] = m;
    ((float4*)ew)[idx] = w;

    if (m.x != 0.f) { d_touched[s.x] = 1; d_touched[d.x] = 1; }
    if (m.y != 0.f) { d_touched[s.y] = 1; d_touched[d.y] = 1; }
    if (m.z != 0.f) { d_touched[s.z] = 1; d_touched[d.z] = 1; }
    if (m.w != 0.f) { d_touched[s.w] = 1; d_touched[d.w] = 1; }
}

// ---------------------------------------------------------------------------
// Kernel 4: node_mask = touched > 0
// ---------------------------------------------------------------------------
__global__ void __launch_bounds__(256)
mask_kernel(float* __restrict__ nm)
{
    const int i = blockIdx.x * 256 + threadIdx.x;
    nm[i] = d_touched[i] ? 1.0f : 0.0f;
}

// ---------------------------------------------------------------------------
// Launch: outputs concatenated as f32 in reference return order:
//   [0,E) edge_mask | [E,2E) edge_weight | [2E,2E+N) logits | [..+N) node_mask
// ---------------------------------------------------------------------------
extern "C" void kernel_launch(void* const* d_in, const int* in_sizes, int n_in,
                              void* d_out, int out_size)
{
    const float* h       = (const float*)d_in[0];
    const float* g       = (const float*)d_in[1];
    const int*   ei      = (const int*)  d_in[2];
    const float* W1      = (const float*)d_in[3];
    const float* b1      = (const float*)d_in[4];
    const float* lngamma = (const float*)d_in[5];
    const float* lnbeta  = (const float*)d_in[6];
    const float* W2      = (const float*)d_in[7];
    const float* b2      = (const float*)d_in[8];

    float* out = (float*)d_out;
    float* em = out;
    float* ew = out + (size_t)NEDGE;
    float* lg = out + 2 * (size_t)NEDGE;
    float* nm = lg + NODES;

    head_kernel<<<NODES / 64, 256>>>(h, g, W1, b1, lngamma, lnbeta, W2, b2, lg);
    topk_kernel<<<BGRAPH, 256>>>(lg);
    edge_kernel<<<NEDGE / 1024, 256>>>(ei, lg, em, ew);
    mask_kernel<<<NODES / 256, 256>>>(nm);
}

// round 6
// speedup vs baseline: 1.2953x; 1.2318x over previous
#include <cuda_runtime.h>
#include <cuda_bf16.h>
#include <cstdint>

// ---------------- problem constants ----------------
#define NODES   262144
#define BGRAPH  1024
#define NPG     256
#define HID     192
#define HID2    384
#define NEDGE   4194304
#define KKEEP   231
#define LN_EPS  1e-5f

// ---------------- head tiling ----------------
#define MTILE   64             // nodes per CTA (64 | 256 -> one graph per CTA)
#define KSTEPS  12             // K = 192 in chunks of 16
// B split global: [kstep 12][split 3][n 384][16 bf16]  (k-contiguous per chunk)
#define B_CHUNK_BYTES  36864   // 3*384*16*2
__device__ __align__(16) unsigned char d_Bsplit[12 * B_CHUNK_BYTES];
__device__ float         d_keep[NODES];
__device__ unsigned char d_touched[NODES];

// ---------------- smem layout ----------------
#define A_PITCH   200                    // bf16 per row (400 B = 16*25 -> ldmatrix conflict-free)
#define A_SPLIT_B (MTILE * A_PITCH * 2)  // 25600 B per split
#define OFF_A     0                      // 3 * 25600 = 76800
#define OFF_B     76800                  // 2 * 36864 = 73728 (double buffer)
#define OFF_PAR   150528                 // b1|gamma|beta|w2 : 4*384*4 = 6144
#define OFF_RS1   156672                 // [64][4] floats = 1024
#define OFF_RS2   157696                 // 1024
#define OFF_RT    158720                 // 1024
#define SMEM_REQ  159744

// ---------------- PTX helpers (all sm_80-era: safe for compute_103) ----------
__device__ __forceinline__ uint32_t smem_u32(const void* p) {
    uint32_t a;
    asm("{ .reg .u64 t; cvta.to.shared.u64 t, %1; cvt.u32.u64 %0, t; }"
        : "=r"(a) : "l"(p));
    return a;
}
__device__ __forceinline__ void ldsm4(uint32_t* r, uint32_t a) {
    asm volatile("ldmatrix.sync.aligned.m8n8.x4.shared.b16 {%0,%1,%2,%3}, [%4];"
                 : "=r"(r[0]), "=r"(r[1]), "=r"(r[2]), "=r"(r[3]) : "r"(a));
}
__device__ __forceinline__ void ldsm2(uint32_t* r, uint32_t a) {
    asm volatile("ldmatrix.sync.aligned.m8n8.x2.shared.b16 {%0,%1}, [%2];"
                 : "=r"(r[0]), "=r"(r[1]) : "r"(a));
}
__device__ __forceinline__ void mma16816(float* d, const uint32_t* a, const uint32_t* b) {
    asm volatile("mma.sync.aligned.m16n8k16.row.col.f32.bf16.bf16.f32 "
                 "{%0,%1,%2,%3}, {%4,%5,%6,%7}, {%8,%9}, {%0,%1,%2,%3};"
                 : "+f"(d[0]), "+f"(d[1]), "+f"(d[2]), "+f"(d[3])
                 : "r"(a[0]), "r"(a[1]), "r"(a[2]), "r"(a[3]),
                   "r"(b[0]), "r"(b[1]));
}
#define CPASYNC16(dst, src) asm volatile("cp.async.cg.shared.global [%0], [%1], 16;" :: "r"(dst), "l"(src))
#define CPCOMMIT()          asm volatile("cp.async.commit_group;" ::: "memory")
#define CPWAIT(n)           asm volatile("cp.async.wait_group %0;" :: "n"(n) : "memory")

// ---------------------------------------------------------------------------
// Prologue: triple-split W1^T (B[n][k] = W1[k][n]) into k-chunked layout:
//   offset = ks*36864 + s*12288 + n*32 + (k&15)*2
// ---------------------------------------------------------------------------
__global__ void __launch_bounds__(256)
wsplit_kernel(const float* __restrict__ W1)
{
    int idx = blockIdx.x * 256 + threadIdx.x;      // 73728 = 288 * 256
    int n = idx % HID2, k = idx / HID2;
    float x = W1[k * HID2 + n];
    __nv_bfloat16 s1 = __float2bfloat16(x);
    float r1 = x - __bfloat162float(s1);
    __nv_bfloat16 s2 = __float2bfloat16(r1);
    float r2 = r1 - __bfloat162float(s2);
    __nv_bfloat16 s3 = __float2bfloat16(r2);

    uint32_t base = (uint32_t)(k >> 4) * B_CHUNK_BYTES + (uint32_t)n * 32u
                  + (uint32_t)(k & 15) * 2u;
    *(__nv_bfloat16*)(d_Bsplit + base)             = s1;
    *(__nv_bfloat16*)(d_Bsplit + base + 12288)     = s2;
    *(__nv_bfloat16*)(d_Bsplit + base + 24576)     = s3;
}

// ---------------------------------------------------------------------------
// Head: 64 nodes x 384 cols per CTA; 8 warps (2 M x 4 N), warp tile 32x96.
// 6-term bf16 HMMA; fused b1 + LayerNorm + ReLU + dot(W2) epilogue.
// ---------------------------------------------------------------------------
__global__ void __launch_bounds__(256, 1)
head_kernel(const float* __restrict__ h, const float* __restrict__ g,
            const float* __restrict__ b1, const float* __restrict__ lngamma,
            const float* __restrict__ lnbeta, const float* __restrict__ W2,
            const float* __restrict__ b2, float* __restrict__ logits)
{
    extern __shared__ char sm[];
    const uint32_t sb = smem_u32(sm);

    const int tid  = threadIdx.x;
    const int wid  = tid >> 5;
    const int lane = tid & 31;
    const int wr   = wid & 1;            // M-warp (2)
    const int wc   = wid >> 1;           // N-warp (4)
    const int n0   = blockIdx.x * MTILE;
    const float b2v = __ldg(b2);

    // ---- params -> smem ----
    {
        float* par = (float*)(sm + OFF_PAR);
        for (int i = tid; i < HID2; i += 256) {
            par[i]            = b1[i];
            par[HID2 + i]     = lngamma[i];
            par[2 * HID2 + i] = lnbeta[i];
            par[3 * HID2 + i] = W2[i];
        }
    }

    // ---- A build: x = h + g[graph], triple split -> smem (pitch 200 bf16) ----
    {
        const float2* h2p = (const float2*)h;
        const int gbase = (n0 >> 8) * HID;
        for (int i = tid; i < MTILE * 96; i += 256) {   // col-pairs
            int row = i / 96, cp = i % 96;
            float2 hv = h2p[(n0 + row) * 96 + cp];
            int c0 = cp * 2;
            float x0 = hv.x + __ldg(&g[gbase + c0]);
            float x1 = hv.y + __ldg(&g[gbase + c0 + 1]);

            __nv_bfloat16 a0 = __float2bfloat16(x0), e0 = __float2bfloat16(x1);
            float ra = x0 - __bfloat162float(a0), rb = x1 - __bfloat162float(e0);
            __nv_bfloat16 a1 = __float2bfloat16(ra), e1 = __float2bfloat16(rb);
            ra -= __bfloat162float(a1); rb -= __bfloat162float(e1);
            __nv_bfloat16 a2 = __float2bfloat16(ra), e2 = __float2bfloat16(rb);

            uint32_t p0 = ((uint32_t)__bfloat16_as_ushort(e0) << 16) | __bfloat16_as_ushort(a0);
            uint32_t p1 = ((uint32_t)__bfloat16_as_ushort(e1) << 16) | __bfloat16_as_ushort(a1);
            uint32_t p2 = ((uint32_t)__bfloat16_as_ushort(e2) << 16) | __bfloat16_as_ushort(a2);

            uint32_t off = (uint32_t)row * (A_PITCH * 2) + (uint32_t)c0 * 2u;
            *(uint32_t*)(sm + OFF_A + off)                 = p0;
            *(uint32_t*)(sm + OFF_A + A_SPLIT_B + off)     = p1;
            *(uint32_t*)(sm + OFF_A + 2 * A_SPLIT_B + off) = p2;
        }
    }

    // ---- cp.async B chunk 0 into buffer 0 ----
    {
        const char* src = (const char*)d_Bsplit;
        for (int i = tid; i < B_CHUNK_BYTES / 16; i += 256)
            CPASYNC16(sb + OFF_B + i * 16, src + i * 16);
        CPCOMMIT();
    }

    // ---- precomputed ldmatrix addresses ----
    // A .x4: quad q: rows + (q&1)*8, cols k0 + (q>>1)*8
    const int q = lane >> 3;
    const uint32_t aRowByte =
        (uint32_t)(wr * 32 + (lane & 7) + ((q & 1) << 3)) * (A_PITCH * 2);
    const uint32_t aColByte = (uint32_t)((q >> 1) << 3) * 2;
    uint32_t aAddr[3][2];
#pragma unroll
    for (int s = 0; s < 3; s++)
#pragma unroll
        for (int m = 0; m < 2; m++)
            aAddr[s][m] = sb + OFF_A + (uint32_t)s * A_SPLIT_B
                        + aRowByte + (uint32_t)m * 16u * (A_PITCH * 2) + aColByte;
    // B .x2: lanes 0-7 -> n rows at k0, lanes 8-15 -> same rows at k0+8
    const uint32_t bLane = (uint32_t)(wc * 96 + (lane & 7)) * 32u + (uint32_t)((lane >> 3) & 1) * 16u;

    float acc[2][12][4];
#pragma unroll
    for (int m = 0; m < 2; m++)
#pragma unroll
        for (int nt = 0; nt < 12; nt++)
#pragma unroll
            for (int j = 0; j < 4; j++) acc[m][nt][j] = 0.f;

    // ---- main loop over 12 k-steps; double-buffered B via cp.async ----
    for (int ks = 0; ks < KSTEPS; ks++) {
        if (ks + 1 < KSTEPS) {
            const char* src = (const char*)(d_Bsplit + (uint32_t)(ks + 1) * B_CHUNK_BYTES);
            const uint32_t dst = sb + OFF_B + (uint32_t)((ks + 1) & 1) * B_CHUNK_BYTES;
            for (int i = tid; i < B_CHUNK_BYTES / 16; i += 256)
                CPASYNC16(dst + i * 16, src + i * 16);
            CPCOMMIT();
            CPWAIT(1);
        } else {
            CPWAIT(0);
        }
        __syncthreads();

        const uint32_t kOff = (uint32_t)ks * 32u;          // k0*2 bytes
        uint32_t Afr[3][2][4];
#pragma unroll
        for (int s = 0; s < 3; s++)
#pragma unroll
            for (int m = 0; m < 2; m++)
                ldsm4(Afr[s][m], aAddr[s][m] + kOff);

        const uint32_t bBase = sb + OFF_B + (uint32_t)(ks & 1) * B_CHUNK_BYTES + bLane;
#pragma unroll
        for (int nt = 0; nt < 12; nt++) {
            uint32_t bf[3][2];
#pragma unroll
            for (int s = 0; s < 3; s++)
                ldsm2(bf[s], bBase + (uint32_t)s * 12288u + (uint32_t)nt * 256u);
#pragma unroll
            for (int m = 0; m < 2; m++) {
                mma16816(acc[m][nt], Afr[0][m], bf[0]);   // a1b1
                mma16816(acc[m][nt], Afr[0][m], bf[1]);   // a1b2
                mma16816(acc[m][nt], Afr[1][m], bf[0]);   // a2b1
                mma16816(acc[m][nt], Afr[1][m], bf[1]);   // a2b2
                mma16816(acc[m][nt], Afr[0][m], bf[2]);   // a1b3
                mma16816(acc[m][nt], Afr[2][m], bf[0]);   // a3b1
            }
        }
        __syncthreads();
    }

    // ---- epilogue: +b1, LN stats, LN+ReLU+dot(W2), logits ----
    const float* par = (const float*)(sm + OFF_PAR);
    float* rs1 = (float*)(sm + OFF_RS1);
    float* rs2 = (float*)(sm + OFF_RS2);
    float* rt  = (float*)(sm + OFF_RT);
    const int l4 = lane >> 2, lm = lane & 3;

    // pass 1: per-row partial moments
#pragma unroll
    for (int m = 0; m < 2; m++)
#pragma unroll
        for (int hf = 0; hf < 2; hf++) {
            float s1 = 0.f, s2 = 0.f;
#pragma unroll
            for (int nt = 0; nt < 12; nt++) {
                const int cb = wc * 96 + nt * 8 + 2 * lm;
                float2 bv = *(const float2*)&par[cb];
                float v0 = acc[m][nt][2 * hf]     + bv.x;
                float v1 = acc[m][nt][2 * hf + 1] + bv.y;
                s1 += v0 + v1; s2 += v0 * v0 + v1 * v1;
            }
            s1 += __shfl_xor_sync(0xffffffffu, s1, 1);
            s1 += __shfl_xor_sync(0xffffffffu, s1, 2);
            s2 += __shfl_xor_sync(0xffffffffu, s2, 1);
            s2 += __shfl_xor_sync(0xffffffffu, s2, 2);
            if (lm == 0) {
                const int row = wr * 32 + m * 16 + hf * 8 + l4;
                rs1[row * 4 + wc] = s1;
                rs2[row * 4 + wc] = s2;
            }
        }
    __syncthreads();

    // pass 2: normalize + relu + dot(W2)
#pragma unroll
    for (int m = 0; m < 2; m++)
#pragma unroll
        for (int hf = 0; hf < 2; hf++) {
            const int row = wr * 32 + m * 16 + hf * 8 + l4;
            const float S1 = rs1[row * 4] + rs1[row * 4 + 1] + rs1[row * 4 + 2] + rs1[row * 4 + 3];
            const float S2 = rs2[row * 4] + rs2[row * 4 + 1] + rs2[row * 4 + 2] + rs2[row * 4 + 3];
            const float mu  = S1 * (1.0f / HID2);
            const float var = S2 * (1.0f / HID2) - mu * mu;
            const float inv = rsqrtf(var + LN_EPS);
            float t = 0.f;
#pragma unroll
            for (int nt = 0; nt < 12; nt++) {
                const int cb = wc * 96 + nt * 8 + 2 * lm;
                float2 bv = *(const float2*)&par[cb];
                float2 gm = *(const float2*)&par[HID2 + cb];
                float2 bt = *(const float2*)&par[2 * HID2 + cb];
                float2 w2 = *(const float2*)&par[3 * HID2 + cb];
                float v0 = acc[m][nt][2 * hf]     + bv.x;
                float v1 = acc[m][nt][2 * hf + 1] + bv.y;
                float z0 = fmaxf((v0 - mu) * inv * gm.x + bt.x, 0.f);
                float z1 = fmaxf((v1 - mu) * inv * gm.y + bt.y, 0.f);
                t += z0 * w2.x + z1 * w2.y;
            }
            t += __shfl_xor_sync(0xffffffffu, t, 1);
            t += __shfl_xor_sync(0xffffffffu, t, 2);
            if (lm == 0) rt[row * 4 + wc] = t;
        }
    __syncthreads();
    if (tid < MTILE)
        logits[n0 + tid] = rt[tid * 4] + rt[tid * 4 + 1] + rt[tid * 4 + 2]
                         + rt[tid * 4 + 3] + b2v;
}

// ---------------------------------------------------------------------------
// Exact per-graph top-k keep mask (jax tie semantics); zeroes touched[].
// ---------------------------------------------------------------------------
__global__ void __launch_bounds__(256)
topk_kernel(const float* __restrict__ logits)
{
    __shared__ float sv[NPG];
    const int node = blockIdx.x * NPG + threadIdx.x;
    const int t = threadIdx.x;
    const float v = logits[node];
    sv[t] = v;
    d_touched[node] = 0;
    __syncthreads();
    int rank = 0;
#pragma unroll 8
    for (int j = 0; j < NPG; j++) {
        const float u = sv[j];
        rank += (u > v) || (u == v && j < t);
    }
    d_keep[node] = (rank < KKEEP) ? 1.0f : 0.0f;
}

// ---------------------------------------------------------------------------
// Edge masking + weights + touched flags (4 edges / thread)
// ---------------------------------------------------------------------------
__global__ void __launch_bounds__(256)
edge_kernel(const int* __restrict__ ei, const float* __restrict__ lg,
            float* __restrict__ em, float* __restrict__ ew)
{
    const int idx = blockIdx.x * 256 + threadIdx.x;
    const int4 s = ((const int4*)ei)[idx];
    const int4 d = ((const int4*)(ei + NEDGE))[idx];

    float4 m, w;
    m.x = d_keep[s.x] * d_keep[d.x];
    m.y = d_keep[s.y] * d_keep[d.y];
    m.z = d_keep[s.z] * d_keep[d.z];
    m.w = d_keep[s.w] * d_keep[d.w];
    w.x = (lg[s.x] + lg[d.x]) * m.x;
    w.y = (lg[s.y] + lg[d.y]) * m.y;
    w.z = (lg[s.z] + lg[d.z]) * m.z;
    w.w = (lg[s.w] + lg[d.w]) * m.w;

    ((float4*)em)[idx] = m;
    ((float4*)ew)[idx] = w;

    if (m.x != 0.f) { d_touched[s.x] = 1; d_touched[d.x] = 1; }
    if (m.y != 0.f) { d_touched[s.y] = 1; d_touched[d.y] = 1; }
    if (m.z != 0.f) { d_touched[s.z] = 1; d_touched[d.z] = 1; }
    if (m.w != 0.f) { d_touched[s.w] = 1; d_touched[d.w] = 1; }
}

__global__ void __launch_bounds__(256)
mask_kernel(float* __restrict__ nm)
{
    const int i = blockIdx.x * 256 + threadIdx.x;
    nm[i] = d_touched[i] ? 1.0f : 0.0f;
}

// ---------------------------------------------------------------------------
// Launch: outputs concatenated f32: edge_mask | edge_weight | logits | node_mask
// ---------------------------------------------------------------------------
extern "C" void kernel_launch(void* const* d_in, const int* in_sizes, int n_in,
                              void* d_out, int out_size)
{
    const float* h       = (const float*)d_in[0];
    const float* g       = (const float*)d_in[1];
    const int*   ei      = (const int*)  d_in[2];
    const float* W1      = (const float*)d_in[3];
    const float* b1      = (const float*)d_in[4];
    const float* lngamma = (const float*)d_in[5];
    const float* lnbeta  = (const float*)d_in[6];
    const float* W2      = (const float*)d_in[7];
    const float* b2      = (const float*)d_in[8];

    float* out = (float*)d_out;
    float* em = out;
    float* ew = out + (size_t)NEDGE;
    float* lg = out + 2 * (size_t)NEDGE;
    float* nm = lg + NODES;

    static int smem_set = 0;
    if (!smem_set) {
        cudaFuncSetAttribute(head_kernel,
                             cudaFuncAttributeMaxDynamicSharedMemorySize, SMEM_REQ);
        smem_set = 1;
    }

    wsplit_kernel<<<(HID * HID2) / 256, 256>>>(W1);
    head_kernel<<<NODES / MTILE, 256, SMEM_REQ>>>(h, g, b1, lngamma, lnbeta, W2, b2, lg);
    topk_kernel<<<BGRAPH, 256>>>(lg);
    edge_kernel<<<NEDGE / 1024, 256>>>(ei, lg, em, ew);
    mask_kernel<<<NODES / 256, 256>>>(nm);
}